// round 16
// baseline (speedup 1.0000x reference)
#include <cuda_runtime.h>
#include <cuda_bf16.h>

#define BB 4
#define NN 16384
#define NPOINT 2048
#define CC 64
#define NS 32
#define OUTC (3 + CC)        // 67
#define GRES 10              // cell size == radius == 0.1
#define NCELL (GRES * GRES * GRES)
#define HITCAP 128           // mean hits ~69 -> ~7 sigma headroom
#define CHCAP 64             // flat chunk descriptors per warp
#define FULLM 0xffffffffu

#define NTILE (NN / 32)                  // 512 n-tiles per batch
#define SCBLOCKS 256                     // scatter blocks (first in k2)
#define K2BLOCKS (SCBLOCKS + BB * NTILE) // 256 + 2048 = 2304

#define SFW 66                           // smem tile row stride (floats)
#define WBYTES (16 * SFW * 4)            // 4224 per warp (16-sample tile)

// ---- device scratch (no allocations allowed) ----
__device__ float  g_feat_t[(size_t)BB * NN * CC];   // features (B, N, C)
__device__ float4 g_pts[BB * NN];                   // cell-sorted (x,y,z,bitcast idx)
__device__ int    g_start[BB * NCELL + 1];          // cell range starts
__device__ int    g_cnt[BB * NCELL];                // histogram; zero at launch entry
__device__ int    g_tick[BB * NCELL];               // scatter tickets; zero at entry

__device__ __forceinline__ int coord_cell(float v) {
    int c = (int)(v * (float)GRES);
    return c < 0 ? 0 : (c > GRES - 1 ? GRES - 1 : c);
}

// ---- K1: histogram, 4 points/thread via 3x LDG.128 (max bytes in flight) ----
__global__ void __launch_bounds__(64) k1_hist(const float* __restrict__ xyz) {
    const int t = blockIdx.x * 64 + threadIdx.x;      // 0..16383
    const float4* __restrict__ v = (const float4*)xyz;
    const float4 a  = v[3 * t + 0];
    const float4 b4 = v[3 * t + 1];
    const float4 c4 = v[3 * t + 2];
    const int cb = ((4 * t) >> 14) * NCELL;           // batch base (4 pts share batch)
    // pt0=(a.x,a.y,a.z) pt1=(a.w,b4.x,b4.y) pt2=(b4.z,b4.w,c4.x) pt3=(c4.y,c4.z,c4.w)
    atomicAdd(&g_cnt[cb + (coord_cell(a.z)  * GRES + coord_cell(a.y))  * GRES + coord_cell(a.x)],  1);
    atomicAdd(&g_cnt[cb + (coord_cell(b4.y) * GRES + coord_cell(b4.x)) * GRES + coord_cell(a.w)],  1);
    atomicAdd(&g_cnt[cb + (coord_cell(c4.x) * GRES + coord_cell(b4.w)) * GRES + coord_cell(b4.z)], 1);
    atomicAdd(&g_cnt[cb + (coord_cell(c4.w) * GRES + coord_cell(c4.z)) * GRES + coord_cell(c4.y)], 1);
}

// ---- K2 (PDL): scatter blocks (0..255, wait on k1) + transpose blocks (no wait) ----
__global__ void __launch_bounds__(256) k2_scatter_transpose(const float* __restrict__ xyz,
                                                            const float* __restrict__ feat) {
    if (blockIdx.x >= SCBLOCKS) {
        // -------- transpose (B,C,N)->(B,N,C), 32n x 64c tile --------
        // Load side: 2x LDG.128/thread (4x in-flight bytes vs scalar).
        // STS banks = (c + 4q + j) mod 32: conflict-free. LDS banks = (4g+i+n): conflict-free.
        __shared__ float tile[CC * 33];
        const int t  = blockIdx.x - SCBLOCKS;
        const int b  = t / NTILE;
        const int n0 = (t % NTILE) * 32;
        const float4* __restrict__ f4 = (const float4*)feat;
        const size_t rowbase = (size_t)(b * CC) * (NN / 4) + (n0 >> 2);
#pragma unroll
        for (int u = 0; u < 2; u++) {
            const int idx = threadIdx.x * 2 + u;      // 0..511
            const int c = idx >> 3;                   // 0..63
            const int q = idx & 7;                    // 0..7
            const float4 val = f4[rowbase + (size_t)c * (NN / 4) + q];
            float* d = &tile[c * 33 + q * 4];
            d[0] = val.x; d[1] = val.y; d[2] = val.z; d[3] = val.w;
        }
        __syncthreads();
        const int n = threadIdx.x >> 3;               // 0..31
        const int g = threadIdx.x & 7;                // 0..7
        float4* __restrict__ dst = (float4*)(g_feat_t + ((size_t)b * NN + n0 + n) * CC);
        const float4 A = make_float4(tile[(4 * g + 0) * 33 + n], tile[(4 * g + 1) * 33 + n],
                                     tile[(4 * g + 2) * 33 + n], tile[(4 * g + 3) * 33 + n]);
        const int g2 = g + 8;
        const float4 B = make_float4(tile[(4 * g2 + 0) * 33 + n], tile[(4 * g2 + 1) * 33 + n],
                                     tile[(4 * g2 + 2) * 33 + n], tile[(4 * g2 + 3) * 33 + n]);
        dst[g]  = A;
        dst[g2] = B;
        return;
    }

    // -------- scatter block: scan + scatter for its slice --------
    __shared__ int s_start[NCELL];
    __shared__ int s_ws[8];
    const int b    = blockIdx.x >> 6;         // 4 batches x 64 blocks
    const int sub  = blockIdx.x & 63;
    const int tid  = threadIdx.x;
    const int lane = tid & 31, warp = tid >> 5;

    // pre-sync: input-only work (overlaps k1 under PDL)
    const int i = b * NN + sub * 256 + tid;
    const float x = xyz[i * 3 + 0];
    const float y = xyz[i * 3 + 1];
    const float z = xyz[i * 3 + 2];
    const int cell = (coord_cell(z) * GRES + coord_cell(y)) * GRES + coord_cell(x);

    cudaGridDependencySynchronize();          // wait for k1's g_cnt

    int vals[4];
    int local = 0;
#pragma unroll
    for (int u = 0; u < 4; u++) {
        const int idx = tid * 4 + u;
        const int c = (idx < NCELL) ? g_cnt[b * NCELL + idx] : 0;
        vals[u] = local;
        local += c;
    }
    int incl = local;
#pragma unroll
    for (int d = 1; d < 32; d <<= 1) {
        int o = __shfl_up_sync(FULLM, incl, d);
        if (lane >= d) incl += o;
    }
    if (lane == 31) s_ws[warp] = incl;
    __syncthreads();
    if (warp == 0 && lane < 8) {
        int ws = s_ws[lane];
#pragma unroll
        for (int d = 1; d < 8; d <<= 1) {
            int o = __shfl_up_sync(0xffu, ws, d);
            if (lane >= d) ws += o;
        }
        s_ws[lane] = ws;
    }
    __syncthreads();
    const int tbase = incl - local + (warp > 0 ? s_ws[warp - 1] : 0);
#pragma unroll
    for (int u = 0; u < 4; u++) {
        const int idx = tid * 4 + u;
        if (idx < NCELL) {
            const int g = b * NN + tbase + vals[u];
            s_start[idx] = g;
            if (sub == 0) g_start[b * NCELL + idx] = g;
        }
    }
    if (blockIdx.x == 0 && tid == 0) g_start[BB * NCELL] = BB * NN;
    __syncthreads();

    const int pos = s_start[cell] + atomicAdd(&g_tick[b * NCELL + cell], 1);
    g_pts[pos] = make_float4(x, y, z, __int_as_float(i & (NN - 1)));
}

// ---- K3 (PDL): ball-query (MLP=4) + packed-key bitonic select + staged grouping ----
__global__ void __launch_bounds__(128) qg_kernel(const float* __restrict__ xyz,
                                                 const float* __restrict__ new_xyz,
                                                 float* __restrict__ out) {
    __shared__ __align__(16) char s_blob[4 * WBYTES];   // 16.9 KB -> 12 blocks/SM

    const int warp = threadIdx.x >> 5;
    const int lane = threadIdx.x & 31;
    const int q    = blockIdx.x * 4 + warp;
    const int b    = q / NPOINT;
    const int p    = q % NPOINT;

    int* s_hits = (int*)(s_blob + warp * WBYTES);   // 128 ints
    int* s_cs   = s_hits + HITCAP;                  // 64 ints
    int* s_ce   = s_cs + CHCAP;                     // 64 ints
    float* s_f  = (float*)(s_blob + warp * WBYTES); // 16 x 66 tile (reuses hits)

    // pre-sync: input-only work (overlaps k2 tail under PDL)
    const float qx = new_xyz[q * 3 + 0];
    const float qy = new_xyz[q * 3 + 1];
    const float qz = new_xyz[q * 3 + 2];
    const float R2 = (float)(0.1 * 0.1);   // f32(0.01), matches reference exactly

    const int cx0 = max(0,        (int)floorf((qx - 0.1f) * (float)GRES - 1e-4f));
    const int cx1 = min(GRES - 1, (int)floorf((qx + 0.1f) * (float)GRES + 1e-4f));
    const int cy0 = max(0,        (int)floorf((qy - 0.1f) * (float)GRES - 1e-4f));
    const int cy1 = min(GRES - 1, (int)floorf((qy + 0.1f) * (float)GRES + 1e-4f));
    const int cz0 = max(0,        (int)floorf((qz - 0.1f) * (float)GRES - 1e-4f));
    const int cz1 = min(GRES - 1, (int)floorf((qz + 0.1f) * (float)GRES + 1e-4f));

    const int ny    = cy1 - cy0 + 1;
    const int nrows = (cz1 - cz0 + 1) * ny;      // <= 9
    int rowbase = 0;
    if (lane < nrows) {
        const int cz = cz0 + lane / ny;
        const int cy = cy0 + lane % ny;
        rowbase = b * NCELL + (cz * GRES + cy) * GRES;
    }

    cudaGridDependencySynchronize();          // wait for k2 (g_start/g_pts/g_feat_t)

    // restore zero-invariants for the next graph replay (k2 done with them)
    if (blockIdx.x < 32) {
        const int z = blockIdx.x * 128 + threadIdx.x;
        if (z < BB * NCELL) g_cnt[z] = 0;
    } else if (blockIdx.x < 64) {
        const int z = (blockIdx.x - 32) * 128 + threadIdx.x;
        if (z < BB * NCELL) g_tick[z] = 0;
    }

    int rs = 0, re = 0;
    if (lane < nrows) {
        rs = g_start[rowbase + cx0];
        re = g_start[rowbase + cx1 + 1];
    }
    const int nch = (lane < nrows) ? (re - rs + 31) >> 5 : 0;
    int pre = nch;
#pragma unroll
    for (int d = 1; d < 32; d <<= 1) {
        int o = __shfl_up_sync(FULLM, pre, d);
        if (lane >= d) pre += o;
    }
    int T = __shfl_sync(FULLM, pre, 31);
    if (T > CHCAP) T = CHCAP;                    // unreachable for this data
    {
        const int excl = pre - nch;
        for (int j = 0; j < nch && excl + j < CHCAP; j++) {
            s_cs[excl + j] = rs + (j << 5);
            s_ce[excl + j] = re;
        }
    }
    __syncwarp();

    int cnt = 0;
    for (int c = 0; c < T; c += 4) {
        float4 pt[4];
        bool   vl[4];
        int    tp[4];
#pragma unroll
        for (int u = 0; u < 4; u++) {
            vl[u] = false;
            if (c + u < T) {
                const int t = s_cs[c + u] + lane;
                tp[u] = t & (NN - 1);            // position within batch
                vl[u] = t < s_ce[c + u];
                if (vl[u]) pt[u] = g_pts[t];
            }
        }
#pragma unroll
        for (int u = 0; u < 4; u++) {
            if (c + u >= T) break;
            bool ok = false; int key = 0;
            if (vl[u]) {
                const float dx = __fsub_rn(qx, pt[u].x);
                const float dy = __fsub_rn(qy, pt[u].y);
                const float dz = __fsub_rn(qz, pt[u].z);
                const float d2 = __fadd_rn(__fadd_rn(__fmul_rn(dx, dx),
                                                     __fmul_rn(dy, dy)),
                                           __fmul_rn(dz, dz));
                ok = d2 < R2;
                key = (__float_as_int(pt[u].w) << 14) | tp[u];   // sorts by idx
            }
            const unsigned m = __ballot_sync(FULLM, ok);
            if (m) {
                const int pos = cnt + __popc(m & ((1u << lane) - 1u));
                if (ok && pos < HITCAP) s_hits[pos] = key;
                cnt += __popc(m);
            }
        }
    }

#pragma unroll
    for (int i = lane; i < HITCAP; i += 32)
        if (i >= cnt) s_hits[i] = 0x7fffffff;    // > any valid key (< 2^28)
    __syncwarp();

    // bitonic sort of 128 keys, 4 regs/lane (ascending)
    int v[4];
#pragma unroll
    for (int r = 0; r < 4; r++) v[r] = s_hits[r * 32 + lane];

#pragma unroll
    for (int k = 2; k <= 128; k <<= 1) {
#pragma unroll
        for (int j = 64; j >= 32; j >>= 1) {
            if (j < k) {
                const int jr = j >> 5;
#pragma unroll
                for (int r = 0; r < 4; r++) {
                    const int pr = r ^ jr;
                    if (pr > r) {
                        const int i = r * 32 + lane;
                        const bool up = ((i & k) == 0);
                        const int a = v[r], c2 = v[pr];
                        const int mn = min(a, c2), mx = max(a, c2);
                        v[r]  = up ? mn : mx;
                        v[pr] = up ? mx : mn;
                    }
                }
            }
        }
#pragma unroll
        for (int j = 16; j >= 1; j >>= 1) {
            if (j < k) {
#pragma unroll
                for (int r = 0; r < 4; r++) {
                    const int i = r * 32 + lane;
                    const int o = __shfl_xor_sync(FULLM, v[r], j);
                    const bool takeMin = (((i & k) == 0) == ((lane & j) == 0));
                    v[r] = takeMin ? min(v[r], o) : max(v[r], o);
                }
            }
        }
    }

    const int c = cnt < NS ? cnt : NS;
    const int firstk = __shfl_sync(FULLM, v[0], 0);
    int idx;
    float px, py, pz;
    if (c > 0) {
        const int kk = (lane < c) ? v[0] : firstk;
        idx = kk >> 14;
        const float4 ptv = g_pts[b * NN + (kk & (NN - 1))];  // == xyz[b][idx], bit-exact
        px = ptv.x; py = ptv.y; pz = ptv.z;
    } else {                                     // no neighbors: reference uses idx 0
        idx = 0;
        const float* __restrict__ x0 = xyz + (size_t)b * NN * 3;
        px = x0[0]; py = x0[1]; pz = x0[2];
    }

    const size_t chan_stride = (size_t)NPOINT * NS;
    const size_t obase2 = (((size_t)b * OUTC) * NPOINT + p) * NS;
    const size_t obase  = obase2 + lane;

    out[obase + 0 * chan_stride] = __fsub_rn(px, qx);
    out[obase + 1 * chan_stride] = __fsub_rn(py, qy);
    out[obase + 2 * chan_stride] = __fsub_rn(pz, qz);

    // 2-pass staged gather/transpose: 16 samples per pass, 16x66 smem tile
    __syncwarp();                        // s_hits fully consumed; s_f may overwrite
    const int half = lane >> 4;          // row parity in gather
    const int c4   = lane & 15;          // float4 slot within 64-ch row
    const int s16  = lane & 15;          // sample within pass (store side)
    const int chp  = lane >> 4;          // channel parity (store side)
#pragma unroll
    for (int pass = 0; pass < 2; pass++) {
#pragma unroll
        for (int j = 0; j < 8; j++) {
            const int row = j * 2 + half;                 // 0..15
            const int s   = pass * 16 + row;
            const int sidx = __shfl_sync(FULLM, idx, s);
            const float4 fv =
                ((const float4*)(g_feat_t + ((size_t)b * NN + sidx) * CC))[c4];
            float* dst = s_f + row * SFW + c4 * 4;
            ((float2*)dst)[0] = make_float2(fv.x, fv.y);
            ((float2*)(dst + 2))[0] = make_float2(fv.z, fv.w);
        }
        __syncwarp();
#pragma unroll
        for (int g = 0; g < 32; g++) {
            const int ch = g * 2 + chp;
            out[obase2 + (size_t)(3 + ch) * chan_stride + pass * 16 + s16] =
                s_f[s16 * SFW + ch];
        }
        __syncwarp();                    // tile reused by next pass
    }
}

extern "C" void kernel_launch(void* const* d_in, const int* in_sizes, int n_in,
                              void* d_out, int out_size) {
    const float* xyz     = (const float*)d_in[0];   // (B, N, 3)
    const float* new_xyz = (const float*)d_in[1];   // (B, NPOINT, 3)
    const float* feat    = (const float*)d_in[2];   // (B, C, N)
    float* out = (float*)d_out;                     // (B, 67, NPOINT, NS)

    k1_hist<<<BB * NN / 4 / 64, 64>>>(xyz);

    cudaLaunchAttribute pdl[1];
    pdl[0].id = cudaLaunchAttributeProgrammaticStreamSerialization;
    pdl[0].val.programmaticStreamSerializationAllowed = 1;

    cudaLaunchConfig_t cfg2 = {};
    cfg2.gridDim  = dim3(K2BLOCKS);                 // 256 scatter + 2048 transpose
    cfg2.blockDim = dim3(256);
    cfg2.attrs    = pdl;
    cfg2.numAttrs = 1;
    cfg2.stream   = 0;
    cudaLaunchKernelEx(&cfg2, k2_scatter_transpose, xyz, feat);

    cudaLaunchConfig_t cfg3 = {};
    cfg3.gridDim  = dim3(BB * NPOINT / 4);          // 2048
    cfg3.blockDim = dim3(128);
    cfg3.attrs    = pdl;
    cfg3.numAttrs = 1;
    cfg3.stream   = 0;
    cudaLaunchKernelEx(&cfg3, qg_kernel, xyz, new_xyz, out);
}